// round 1
// baseline (speedup 1.0000x reference)
#include <cuda_runtime.h>
#include <math.h>

// ---------------- scratch (device globals; no runtime allocation) ----------------
static __device__ float g_x1[4096 * 64];          //  1 MB
static __device__ float g_x2[4096 * 256];         //  4 MB
static __device__ float g_x3[4096 * 1024];        // 16 MB
static __device__ float g_x4[4096 * 4096];        // 64 MB  == (B, C=64, N=64)
static __device__ float g_t1[4096 * 128 * 64];    // 128 MB
static __device__ float g_t2[4096 * 256 * 64];    // 256 MB

__device__ __forceinline__ float leaky(float v) { return v > 0.f ? v : 0.01f * v; }

// ---------------- MLP GEMM: C = leaky(A(M,K) * W(N,K)^T + bias) ----------------
// BM=128, BN=64, BK=16, thread tile 8x8, 128 threads. M=4096, K%16==0, N%64==0.
__global__ void __launch_bounds__(128)
gemm_bias_leaky(const float* __restrict__ A, const float* __restrict__ W,
                const float* __restrict__ bias, float* __restrict__ C,
                int K, int N)
{
    __shared__ float As[16][128];
    __shared__ float Ws[16][64];

    const int tid = threadIdx.x;
    const int mt = tid & 15;      // 0..15 -> m tile (8 rows)
    const int nt = tid >> 4;      // 0..7  -> n tile (8 cols)

    const float* Ab = A + (size_t)blockIdx.x * 128 * K;
    const float* Wb = W + (size_t)blockIdx.y * 64 * K;

    float acc[8][8] = {};

    for (int k0 = 0; k0 < K; k0 += 16) {
        // load A tile (128 x 16), transposed into As[k][m]
        #pragma unroll
        for (int i = 0; i < 4; i++) {
            int lin = tid + i * 128;
            int r = lin >> 2, c4 = lin & 3;
            float4 v = *(const float4*)(Ab + (size_t)r * K + k0 + c4 * 4);
            As[c4 * 4 + 0][r] = v.x;
            As[c4 * 4 + 1][r] = v.y;
            As[c4 * 4 + 2][r] = v.z;
            As[c4 * 4 + 3][r] = v.w;
        }
        // load W tile (64 x 16), transposed into Ws[k][n]
        #pragma unroll
        for (int i = 0; i < 2; i++) {
            int lin = tid + i * 128;
            int r = lin >> 2, c4 = lin & 3;
            float4 v = *(const float4*)(Wb + (size_t)r * K + k0 + c4 * 4);
            Ws[c4 * 4 + 0][r] = v.x;
            Ws[c4 * 4 + 1][r] = v.y;
            Ws[c4 * 4 + 2][r] = v.z;
            Ws[c4 * 4 + 3][r] = v.w;
        }
        __syncthreads();

        #pragma unroll
        for (int kk = 0; kk < 16; kk++) {
            float a[8], w[8];
            *(float4*)&a[0] = *(const float4*)&As[kk][mt * 8];
            *(float4*)&a[4] = *(const float4*)&As[kk][mt * 8 + 4];
            *(float4*)&w[0] = *(const float4*)&Ws[kk][nt * 8];
            *(float4*)&w[4] = *(const float4*)&Ws[kk][nt * 8 + 4];
            #pragma unroll
            for (int i = 0; i < 8; i++)
                #pragma unroll
                for (int j = 0; j < 8; j++)
                    acc[i][j] = fmaf(a[i], w[j], acc[i][j]);
        }
        __syncthreads();
    }

    float bv[8];
    #pragma unroll
    for (int j = 0; j < 8; j++) bv[j] = __ldg(&bias[blockIdx.y * 64 + nt * 8 + j]);

    #pragma unroll
    for (int i = 0; i < 8; i++) {
        size_t row = (size_t)(blockIdx.x * 128 + mt * 8 + i) * N + blockIdx.y * 64 + nt * 8;
        float4 o0, o1;
        o0.x = leaky(acc[i][0] + bv[0]); o0.y = leaky(acc[i][1] + bv[1]);
        o0.z = leaky(acc[i][2] + bv[2]); o0.w = leaky(acc[i][3] + bv[3]);
        o1.x = leaky(acc[i][4] + bv[4]); o1.y = leaky(acc[i][5] + bv[5]);
        o1.z = leaky(acc[i][6] + bv[6]); o1.w = leaky(acc[i][7] + bv[7]);
        *(float4*)&C[row]     = o0;
        *(float4*)&C[row + 4] = o1;
    }
}

// ---------------- fused tree_conv + bias + LayerNorm + LeakyReLU ----------------
// One CTA per sample. THREADS == O. Thread tile: 8 outputs (o strided by OT) x 8 nodes.
// smem: xs[C*64] | ws[24*O] (8-channel W chunk) | idxs[192] | red[64]
template <int C, int O>
__global__ void __launch_bounds__(O, 1)
conv_ln(const float* __restrict__ xin, const int* __restrict__ idxg,
        const float* __restrict__ w, const float* __restrict__ bias,
        float* __restrict__ out)
{
    constexpr int OT = O / 8;
    extern __shared__ float sm[];
    float* xs   = sm;                       // C*64 floats
    float* ws   = xs + C * 64;              // 24*O floats
    int*   idxs = (int*)(ws + 24 * O);      // 192 ints
    float* red  = (float*)(idxs + 192);     // 64 floats

    const int tid = threadIdx.x;
    const int b   = blockIdx.x;
    const int ot  = tid % OT;
    const int nt  = tid / OT;

    for (int i = tid; i < 189; i += O) idxs[i] = idxg[(size_t)b * 189 + i];
    {
        const float4* xi = (const float4*)(xin + (size_t)b * (C * 64));
        float4* xd = (float4*)xs;
        for (int i = tid; i < C * 16; i += O) xd[i] = xi[i];
    }
    __syncthreads();

    // per-thread gather indices for its 8 nodes (node 63 is a pad lane)
    int off[3][8];
    #pragma unroll
    for (int j = 0; j < 8; j++) {
        int node = nt * 8 + j;
        int base = (node < 63) ? 3 * node : 0;
        off[0][j] = idxs[base];
        off[1][j] = idxs[base + 1];
        off[2][j] = idxs[base + 2];
    }

    float acc[8][8] = {};

    const float4* wg = (const float4*)(w + (size_t)tid * (3 * C)); // row o = tid
    for (int c0 = 0; c0 < C; c0 += 8) {
        __syncthreads();
        // stage W chunk: channels [c0, c0+8), all O rows -> ws[(cc*3+kk)][o]
        #pragma unroll
        for (int q = 0; q < 6; q++) {
            float4 v = wg[(c0 * 3) / 4 + q];
            int l = q * 4;
            ws[(l + 0) * O + tid] = v.x;
            ws[(l + 1) * O + tid] = v.y;
            ws[(l + 2) * O + tid] = v.z;
            ws[(l + 3) * O + tid] = v.w;
        }
        __syncthreads();

        #pragma unroll 2
        for (int cc = 0; cc < 8; cc++) {
            int cb = (c0 + cc) * 64;
            #pragma unroll
            for (int kk = 0; kk < 3; kk++) {
                const float* wr = ws + (cc * 3 + kk) * O + ot;
                float wv[8], ev[8];
                #pragma unroll
                for (int i = 0; i < 8; i++) wv[i] = wr[i * OT];      // conflict-free LDS
                #pragma unroll
                for (int j = 0; j < 8; j++) ev[j] = xs[cb + off[kk][j]]; // warp broadcast
                #pragma unroll
                for (int i = 0; i < 8; i++)
                    #pragma unroll
                    for (int j = 0; j < 8; j++)
                        acc[i][j] = fmaf(wv[i], ev[j], acc[i][j]);
            }
        }
    }

    // bias + local LN stats (zero column 0 contributes nothing to sums)
    float bv[8];
    #pragma unroll
    for (int i = 0; i < 8; i++) bv[i] = __ldg(&bias[ot + i * OT]);

    float s = 0.f, ss = 0.f;
    #pragma unroll
    for (int i = 0; i < 8; i++)
        #pragma unroll
        for (int j = 0; j < 8; j++) {
            float v = acc[i][j] + bv[i];
            acc[i][j] = v;
            if (nt * 8 + j < 63) { s += v; ss += v * v; }
        }

    const int lane = tid & 31, warp = tid >> 5;
    #pragma unroll
    for (int sh = 16; sh; sh >>= 1) {
        s  += __shfl_down_sync(0xffffffffu, s,  sh);
        ss += __shfl_down_sync(0xffffffffu, ss, sh);
    }
    if (lane == 0) { red[2 * warp] = s; red[2 * warp + 1] = ss; }
    __syncthreads();
    if (tid == 0) {
        float S = 0.f, SS = 0.f;
        for (int wi = 0; wi < O / 32; wi++) { S += red[2 * wi]; SS += red[2 * wi + 1]; }
        const float nn = (float)(O * 64);
        float mean = S / nn;
        float var = (SS - nn * mean * mean) / (nn - 1.f);
        var = fmaxf(var, 0.f);
        float scale = 1.f / (sqrtf(var) + 1e-5f);
        red[0] = mean; red[1] = scale;
    }
    __syncthreads();
    const float mean = red[0], scale = red[1];
    const float z0 = leaky((0.f - mean) * scale);

    float* po = out + (size_t)b * (O * 64);
    #pragma unroll
    for (int i = 0; i < 8; i++) {
        float* row = po + (ot + i * OT) * 64;
        if (nt == 0) row[0] = z0;
        #pragma unroll
        for (int j = 0; j < 8; j++) {
            int node = nt * 8 + j;
            if (node < 63) row[node + 1] = leaky((acc[i][j] - mean) * scale);
        }
    }
}

// ---------------- host launch ----------------
static constexpr size_t SMEM1 = (64 * 64  + 24 * 128 + 192 + 64) * 4;  // ~29.7 KB
static constexpr size_t SMEM2 = (128 * 64 + 24 * 256 + 192 + 64) * 4;  // ~58.4 KB
static constexpr size_t SMEM3 = (256 * 64 + 24 * 512 + 192 + 64) * 4;  // ~115.7 KB

extern "C" void kernel_launch(void* const* d_in, const int* in_sizes, int n_in,
                              void* d_out, int out_size)
{
    const float* trees   = (const float*)d_in[0];
    const int*   indexes = (const int*)  d_in[1];
    const float* W1 = (const float*)d_in[2];  const float* b1 = (const float*)d_in[3];
    const float* W2 = (const float*)d_in[4];  const float* b2 = (const float*)d_in[5];
    const float* W3 = (const float*)d_in[6];  const float* b3 = (const float*)d_in[7];
    const float* W4 = (const float*)d_in[8];  const float* b4 = (const float*)d_in[9];
    const float* cw1 = (const float*)d_in[10]; const float* cb1 = (const float*)d_in[11];
    const float* cw2 = (const float*)d_in[12]; const float* cb2 = (const float*)d_in[13];
    const float* cw3 = (const float*)d_in[14]; const float* cb3 = (const float*)d_in[15];

    float *x1, *x2, *x3, *x4, *t1, *t2;
    cudaGetSymbolAddress((void**)&x1, g_x1);
    cudaGetSymbolAddress((void**)&x2, g_x2);
    cudaGetSymbolAddress((void**)&x3, g_x3);
    cudaGetSymbolAddress((void**)&x4, g_x4);
    cudaGetSymbolAddress((void**)&t1, g_t1);
    cudaGetSymbolAddress((void**)&t2, g_t2);

    cudaFuncSetAttribute(conv_ln<64, 128>,  cudaFuncAttributeMaxDynamicSharedMemorySize, (int)SMEM1);
    cudaFuncSetAttribute(conv_ln<128, 256>, cudaFuncAttributeMaxDynamicSharedMemorySize, (int)SMEM2);
    cudaFuncSetAttribute(conv_ln<256, 512>, cudaFuncAttributeMaxDynamicSharedMemorySize, (int)SMEM3);

    // MLP: 16 -> 64 -> 256 -> 1024 -> 4096 (leaky after each)
    gemm_bias_leaky<<<dim3(32, 1),  128>>>(trees, W1, b1, x1, 16,   64);
    gemm_bias_leaky<<<dim3(32, 4),  128>>>(x1,    W2, b2, x2, 64,   256);
    gemm_bias_leaky<<<dim3(32, 16), 128>>>(x2,    W3, b3, x3, 256,  1024);
    gemm_bias_leaky<<<dim3(32, 64), 128>>>(x3,    W4, b4, x4, 1024, 4096);

    // Fused conv + LN + leaky blocks (one CTA per sample)
    conv_ln<64, 128> <<<4096, 128, SMEM1>>>(x4, indexes, cw1, cb1, t1);
    conv_ln<128, 256><<<4096, 256, SMEM2>>>(t1, indexes, cw2, cb2, t2);
    conv_ln<256, 512><<<4096, 512, SMEM3>>>(t2, indexes, cw3, cb3, (float*)d_out);
}